// round 8
// baseline (speedup 1.0000x reference)
#include <cuda_runtime.h>
#include <cuda_bf16.h>

// CALayer SE, single-pass persistent pipelined kernel, smem retention.
// 1024 co-resident blocks (LB(256,7); smem 16KB+static x7 = ~121KB/SM OK).
// Per round r: (1) issue round-r chunk loads into registers (in flight),
// (2) gate_scale(r-1): spin on counter (hidden by in-flight loads), MLP,
//     scale the smem-retained r-1 chunk, st.cs out,
// (3) consume registers: sum, store chunk to smem, publish counter r.
// x read from DRAM exactly once; second read served by smem. Traffic 537MB.

#define BATCH 16
#define CHAN 256
#define CR 16
#define HW 16384               // floats per plane
#define PLANE_F4 (HW/4)        // 4096
#define QF4 (PLANE_F4/4)       // 1024 float4 per quarter chunk
#define NBLK 1024
#define TPB 256

__device__ float g_part[BATCH * CHAN * 4];
__device__ int   g_cnt[BATCH];

__global__ void init_kernel() {
    if (threadIdx.x < BATCH) g_cnt[threadIdx.x] = 0;
}

__device__ __forceinline__ void stcs4(float4* p, float4 v) {
    asm volatile("st.global.cs.v4.f32 [%0], {%1,%2,%3,%4};"
                 :: "l"(p), "f"(v.x), "f"(v.y), "f"(v.z), "f"(v.w) : "memory");
}

__global__ __launch_bounds__(TPB, 7) void fused_se_kernel(
    const float* __restrict__ x, float* __restrict__ out,
    const float* __restrict__ w1, const float* __restrict__ b1,
    const float* __restrict__ w2, const float* __restrict__ b2)
{
    __shared__ float4 schunk[QF4];     // 16KB: retained quarter-plane chunk
    __shared__ float sred[8];
    __shared__ float smean[CHAN];
    __shared__ float shid[CR];
    __shared__ float sscale;

    const int chan    = blockIdx.x >> 2;   // 0..255
    const int quarter = blockIdx.x & 3;    // 0..3
    const int tid  = threadIdx.x;
    const int lane = tid & 31;
    const int wid  = tid >> 5;
    const size_t qoff = (size_t)quarter * QF4;

    const float4* __restrict__ x4 = reinterpret_cast<const float4*>(x);
    float4* __restrict__ o4 = reinterpret_cast<float4*>(out);

    // consume registers: sum, stash to smem, publish counter for batch b
    auto finish_round = [&](int b, float4 v0, float4 v1, float4 v2, float4 v3) {
        float acc = ((v0.x + v0.y) + (v0.z + v0.w))
                  + ((v1.x + v1.y) + (v1.z + v1.w))
                  + ((v2.x + v2.y) + (v2.z + v2.w))
                  + ((v3.x + v3.y) + (v3.z + v3.w));
        schunk[tid          ] = v0;
        schunk[tid +     TPB] = v1;
        schunk[tid + 2 * TPB] = v2;
        schunk[tid + 3 * TPB] = v3;
        #pragma unroll
        for (int o = 16; o; o >>= 1) acc += __shfl_xor_sync(0xFFFFFFFF, acc, o);
        if (lane == 0) sred[wid] = acc;
        __syncthreads();
        if (tid == 0) {
            float t = 0.f;
            #pragma unroll
            for (int w = 0; w < 8; w++) t += sred[w];
            g_part[(((b << 8) | chan) << 2) + quarter] = t;
            __threadfence();
            atomicAdd(&g_cnt[b], 1);
        }
    };

    auto gate_scale = [&](int b) {
        if (tid == 0) {
            while (atomicAdd(&g_cnt[b], 0) < NBLK) __nanosleep(64);
            __threadfence();
        }
        __syncthreads();
        {
            const int q = (((b << 8) + tid)) * 4;
            smean[tid] = (__ldcg(&g_part[q]) + __ldcg(&g_part[q + 1]) +
                          __ldcg(&g_part[q + 2]) + __ldcg(&g_part[q + 3])) * (1.0f / HW);
        }
        __syncthreads();
        #pragma unroll
        for (int k = 0; k < 2; k++) {
            const int r = wid * 2 + k;
            float acc = 0.f;
            #pragma unroll
            for (int c = lane; c < CHAN; c += 32)
                acc += __ldg(&w1[r * CHAN + c]) * smean[c];
            #pragma unroll
            for (int o = 16; o; o >>= 1) acc += __shfl_xor_sync(0xFFFFFFFF, acc, o);
            if (lane == 0) shid[r] = fmaxf(acc + __ldg(&b1[r]), 0.f);
        }
        __syncthreads();
        if (tid == 0) {
            float acc = __ldg(&b2[chan]);
            #pragma unroll
            for (int r = 0; r < CR; r++)
                acc += __ldg(&w2[chan * CR + r]) * shid[r];
            sscale = 1.0f / (1.0f + __expf(-acc));
        }
        __syncthreads();
        // scale smem-retained chunk, stream out
        const float sc = sscale;
        const int p = (b << 8) | chan;
        float4* __restrict__ op = o4 + (size_t)p * PLANE_F4 + qoff;
        #pragma unroll
        for (int i = 0; i < 4; i++) {
            float4 v = schunk[tid + i * TPB];
            v.x *= sc; v.y *= sc; v.z *= sc; v.w *= sc;
            stcs4(&op[tid + i * TPB], v);
        }
        __syncthreads();   // chunk consumed; safe to overwrite
    };

    // ---------- prologue: round 0 ----------
    {
        const float4* __restrict__ xp = x4 + (size_t)chan * PLANE_F4 + qoff;
        float4 v0 = xp[tid], v1 = xp[tid + TPB], v2 = xp[tid + 2*TPB], v3 = xp[tid + 3*TPB];
        finish_round(0, v0, v1, v2, v3);
    }

    // ---------- pipelined main loop ----------
    for (int b = 1; b < BATCH; b++) {
        // (1) issue round-b loads; kept in flight across gate_scale(b-1)
        const float4* __restrict__ xp =
            x4 + (size_t)((b << 8) | chan) * PLANE_F4 + qoff;
        float4 v0 = xp[tid];
        float4 v1 = xp[tid + TPB];
        float4 v2 = xp[tid + 2 * TPB];
        float4 v3 = xp[tid + 3 * TPB];

        // (2) previous round: gate + scale from smem (overlaps the loads)
        gate_scale(b - 1);

        // (3) consume loads: sum, retain in smem, publish
        finish_round(b, v0, v1, v2, v3);
    }

    gate_scale(BATCH - 1);
}

extern "C" void kernel_launch(void* const* d_in, const int* in_sizes, int n_in,
                              void* d_out, int out_size) {
    const float* x  = (const float*)d_in[0];
    const float* w1 = (const float*)d_in[1];
    const float* b1 = (const float*)d_in[2];
    const float* w2 = (const float*)d_in[3];
    const float* b2 = (const float*)d_in[4];
    float* out = (float*)d_out;

    init_kernel<<<1, 32>>>();
    fused_se_kernel<<<NBLK, TPB>>>(x, out, w1, b1, w2, b2);
}

// round 10
// speedup vs baseline: 1.0065x; 1.0065x over previous
#include <cuda_runtime.h>
#include <cuda_bf16.h>
#include <cstdint>

// CALayer SE, single-pass persistent kernel, cp.async-pipelined smem ring.
// 1024 co-resident blocks (LB(256,7); 7x148=1036 slots). Each block owns a
// quarter-plane (16KB) per batch, retained in a 3x8KB smem segment ring.
// Round b (data of b in segs s,s+1; seg s+2 free):
//   1. cp.async first half of batch b+1 -> free seg   (DRAM busy during gate)
//   2. gate(b): spin counter, means, tiny MLP -> scale factor
//   3. scale+store seg s; per-slot cp.async second half of b+1 into seg s
//   4. scale+store seg s+1
//   5. wait cp.async; sum batch b+1 from smem; publish counter
// x read from DRAM once (via cp.async), scaled copy read from smem. 537MB.

#define BATCH 16
#define CHAN 256
#define CR 16
#define HW 16384                 // floats per plane
#define PLANE_F4 (HW/4)          // 4096
#define QF4 (PLANE_F4/4)         // 1024 float4 per quarter chunk
#define SEG_F4 (QF4/2)           // 512 float4 per 8KB segment
#define NBLK 1024
#define TPB 256

__device__ float g_part[BATCH * CHAN * 4];
__device__ int   g_cnt[BATCH];

__global__ void init_kernel() {
    if (threadIdx.x < BATCH) g_cnt[threadIdx.x] = 0;
}

__device__ __forceinline__ void stcs4(float4* p, float4 v) {
    asm volatile("st.global.cs.v4.f32 [%0], {%1,%2,%3,%4};"
                 :: "l"(p), "f"(v.x), "f"(v.y), "f"(v.z), "f"(v.w) : "memory");
}
__device__ __forceinline__ void cpasync16(unsigned int dst_smem, const void* src) {
    asm volatile("cp.async.cg.shared.global [%0], [%1], 16;"
                 :: "r"(dst_smem), "l"(src) : "memory");
}
__device__ __forceinline__ void cpasync_commit() {
    asm volatile("cp.async.commit_group;" ::: "memory");
}
__device__ __forceinline__ void cpasync_wait_all() {
    asm volatile("cp.async.wait_group 0;" ::: "memory");
}
__device__ __forceinline__ unsigned int smem_u32(const void* p) {
    unsigned int a;
    asm("{ .reg .u64 t; cvta.to.shared.u64 t, %1; cvt.u32.u64 %0, t; }"
        : "=r"(a) : "l"(p));
    return a;
}

__global__ __launch_bounds__(TPB, 7) void fused_se_kernel(
    const float* __restrict__ x, float* __restrict__ out,
    const float* __restrict__ w1, const float* __restrict__ b1,
    const float* __restrict__ w2, const float* __restrict__ b2)
{
    __shared__ float4 ring[3 * SEG_F4];    // 24KB
    __shared__ float sred[8];
    __shared__ float smean[CHAN];
    __shared__ float shid[CR];
    __shared__ float sscale;

    const int chan    = blockIdx.x >> 2;
    const int quarter = blockIdx.x & 3;
    const int tid  = threadIdx.x;
    const int lane = tid & 31;
    const int wid  = tid >> 5;
    const size_t qoff = (size_t)quarter * QF4;

    const float4* __restrict__ x4 = reinterpret_cast<const float4*>(x);
    float4* __restrict__ o4 = reinterpret_cast<float4*>(out);
    const unsigned int ring_base = smem_u32(ring);

    // gmem base of batch b's chunk for this block
    auto chunk_ptr = [&](int b) {
        return x4 + (size_t)((b << 8) | chan) * PLANE_F4 + qoff;
    };

    // sum segs (segL=first half, segH=second half), publish counter b
    auto sum_publish = [&](int b, int segL, int segH) {
        float4 a0 = ring[segL * SEG_F4 + tid];
        float4 a1 = ring[segL * SEG_F4 + tid + TPB];
        float4 a2 = ring[segH * SEG_F4 + tid];
        float4 a3 = ring[segH * SEG_F4 + tid + TPB];
        float acc = ((a0.x + a0.y) + (a0.z + a0.w))
                  + ((a1.x + a1.y) + (a1.z + a1.w))
                  + ((a2.x + a2.y) + (a2.z + a2.w))
                  + ((a3.x + a3.y) + (a3.z + a3.w));
        #pragma unroll
        for (int o = 16; o; o >>= 1) acc += __shfl_xor_sync(0xFFFFFFFF, acc, o);
        if (lane == 0) sred[wid] = acc;
        __syncthreads();
        if (tid == 0) {
            float t = 0.f;
            #pragma unroll
            for (int w = 0; w < 8; w++) t += sred[w];
            g_part[(((b << 8) | chan) << 2) + quarter] = t;
            __threadfence();
            atomicAdd(&g_cnt[b], 1);
        }
    };

    // gate: wait for all partials of b, compute means + MLP -> sscale
    auto gate = [&](int b) {
        if (tid == 0) {
            while (atomicAdd(&g_cnt[b], 0) < NBLK) __nanosleep(64);
            __threadfence();
        }
        __syncthreads();
        {
            const int q = ((b << 8) + tid) * 4;
            smean[tid] = (__ldcg(&g_part[q]) + __ldcg(&g_part[q + 1]) +
                          __ldcg(&g_part[q + 2]) + __ldcg(&g_part[q + 3])) * (1.0f / HW);
        }
        __syncthreads();
        #pragma unroll
        for (int k = 0; k < 2; k++) {
            const int r = wid * 2 + k;
            float acc = 0.f;
            #pragma unroll
            for (int c = lane; c < CHAN; c += 32)
                acc += __ldg(&w1[r * CHAN + c]) * smean[c];
            #pragma unroll
            for (int o = 16; o; o >>= 1) acc += __shfl_xor_sync(0xFFFFFFFF, acc, o);
            if (lane == 0) shid[r] = fmaxf(acc + __ldg(&b1[r]), 0.f);
        }
        __syncthreads();
        if (tid == 0) {
            float acc = __ldg(&b2[chan]);
            #pragma unroll
            for (int r = 0; r < CR; r++)
                acc += __ldg(&w2[chan * CR + r]) * shid[r];
            sscale = 1.0f / (1.0f + __expf(-acc));
        }
        __syncthreads();
    };

    // scale+store one segment of batch b's chunk; halfIdx: 0 or 1 within chunk
    auto scale_seg = [&](int b, int seg, int halfIdx, float sc) {
        float4* __restrict__ op =
            o4 + (size_t)((b << 8) | chan) * PLANE_F4 + qoff + halfIdx * SEG_F4;
        #pragma unroll
        for (int i = 0; i < 2; i++) {
            float4 v = ring[seg * SEG_F4 + tid + i * TPB];
            v.x *= sc; v.y *= sc; v.z *= sc; v.w *= sc;
            stcs4(&op[tid + i * TPB], v);
        }
    };

    // cp.async one half (halfIdx) of batch b's chunk into segment seg
    auto fetch_half = [&](int b, int seg, int halfIdx) {
        const float4* src = chunk_ptr(b) + halfIdx * SEG_F4;
        #pragma unroll
        for (int i = 0; i < 2; i++) {
            cpasync16(ring_base + (seg * SEG_F4 + tid + i * TPB) * 16,
                      src + tid + i * TPB);
        }
        cpasync_commit();
    };

    // ---------- prologue: fetch batch 0 into segs 0,1 ----------
    fetch_half(0, 0, 0);
    fetch_half(0, 1, 1);
    cpasync_wait_all();
    __syncthreads();
    sum_publish(0, 0, 1);

    // ---------- main loop ----------
    int s = 0;   // batch b lives in segs (s, s+1)%3
    for (int b = 0; b < BATCH - 1; b++) {
        const int segA = s;
        const int segB = (s + 1) % 3;
        const int segC = (s + 2) % 3;

        fetch_half(b + 1, segC, 0);      // (1) read overlaps gate
        gate(b);                          // (2)
        const float sc = sscale;
        scale_seg(b, segA, 0, sc);        // (3) consume segA...
        fetch_half(b + 1, segA, 1);       //     ...then refill with b+1 2nd half
        scale_seg(b, segB, 1, sc);        // (4)
        cpasync_wait_all();               // (5)
        __syncthreads();
        sum_publish(b + 1, segC, segA);   // b+1: first half in segC, second in segA

        s = (s + 2) % 3;
    }

    // ---------- epilogue: last batch ----------
    gate(BATCH - 1);
    {
        const float sc = sscale;
        scale_seg(BATCH - 1, s, 0, sc);
        scale_seg(BATCH - 1, (s + 1) % 3, 1, sc);
    }
}

extern "C" void kernel_launch(void* const* d_in, const int* in_sizes, int n_in,
                              void* d_out, int out_size) {
    const float* x  = (const float*)d_in[0];
    const float* w1 = (const float*)d_in[1];
    const float* b1 = (const float*)d_in[2];
    const float* w2 = (const float*)d_in[3];
    const float* b2 = (const float*)d_in[4];
    float* out = (float*)d_out;

    init_kernel<<<1, 32>>>();
    fused_se_kernel<<<NBLK, TPB>>>(x, out, w1, b1, w2, b2);
}